// round 5
// baseline (speedup 1.0000x reference)
#include <cuda_runtime.h>
#include <cstdint>

#define NN 50000
#define NE 640000
#define IND 128
#define OUTD 128
#define NH 4
#define HD 32

// -------- scratch --------
__device__ __align__(16) float g_Wh[(size_t)NN * OUTD];    // 25.6 MB
__device__ __align__(16) float g_s1[NN * NH];
__device__ __align__(16) float g_s2[NN * NH];
__device__ __align__(16) int   g_src[NE];
__device__ __align__(16) int   g_dst[NE];
__device__ __align__(16) int   g_deg[NN];
__device__ __align__(16) int   g_off[NN + 1];
__device__ __align__(16) int   g_cur[NN];
__device__ __align__(16) int2  g_csr[NE];   // {src, edge_id} grouped by dst
__device__ int g_is64;

// -------- detect edge_index width: int64 → high words all zero --------
__global__ void k_detect(const void* __restrict__ ei) {
    if (threadIdx.x == 0 && blockIdx.x == 0) {
        const uint2* p = (const uint2*)ei;
        int is64 = 1;
        for (int i = 0; i < 1024; i++) {
            if (p[i].y != 0u) { is64 = 0; break; }
        }
        g_is64 = is64;
    }
}

// -------- decode edge_index into clamped int32 src/dst --------
__global__ void k_decode(const void* __restrict__ ei) {
    int i = blockIdx.x * blockDim.x + threadIdx.x;
    if (i >= 2 * NE) return;
    long long v;
    if (g_is64) v = ((const long long*)ei)[i];
    else        v = (long long)((const int*)ei)[i];
    int iv = (int)v;
    iv = iv < 0 ? 0 : (iv >= NN ? NN - 1 : iv);
    if (i < NE) g_src[i] = iv;
    else        g_dst[i - NE] = iv;
}

// -------- zero degree counts --------
__global__ void k_zero() {
    int i = blockIdx.x * blockDim.x + threadIdx.x;
    if (i < NN) g_deg[i] = 0;
}

// -------- count in-degree --------
__global__ void k_count() {
    int i = blockIdx.x * blockDim.x + threadIdx.x;
    if (i >= NE) return;
    atomicAdd(&g_deg[g_dst[i]], 1);
}

// -------- single-block prefix scan over 50000 degrees --------
__global__ void k_scan() {
    __shared__ int part[1024];
    int t = threadIdx.x;
    const int C = (NN + 1023) / 1024;  // 49
    int beg = t * C;
    int end = beg + C; if (end > NN) end = NN; if (beg > NN) beg = NN;
    int s = 0;
    for (int i = beg; i < end; i++) s += g_deg[i];
    part[t] = s;
    __syncthreads();
    for (int o = 1; o < 1024; o <<= 1) {
        int v = (t >= o) ? part[t - o] : 0;
        __syncthreads();
        part[t] += v;
        __syncthreads();
    }
    int run = (t == 0) ? 0 : part[t - 1];
    for (int i = beg; i < end; i++) {
        g_off[i] = run;
        g_cur[i] = run;
        run += g_deg[i];
    }
    if (t == 1023) g_off[NN] = run;
}

// -------- scatter edges into CSR buckets --------
__global__ void k_fill() {
    int i = blockIdx.x * blockDim.x + threadIdx.x;
    if (i >= NE) return;
    int d = g_dst[i];
    int pos = atomicAdd(&g_cur[d], 1);
    g_csr[pos] = make_int2(g_src[i], i);
}

// -------- GEMM: Wh = h @ W^T, fused s1/s2 attention dots --------
__global__ void k_gemm(const float* __restrict__ h, const float* __restrict__ W,
                       const float* __restrict__ a) {
    __shared__ float Ws[32][128];
    __shared__ float Hs[64][32];

    int t = threadIdx.x;
    int tx = t & 31;
    int ty = t >> 5;
    int rbase = blockIdx.x * 64;

    float acc[8][4];
#pragma unroll
    for (int i = 0; i < 8; i++)
#pragma unroll
        for (int j = 0; j < 4; j++) acc[i][j] = 0.f;

    for (int kc = 0; kc < 128; kc += 32) {
        __syncthreads();
        {
            int c = t >> 1;
            int k0 = (t & 1) * 16;
#pragma unroll
            for (int j = 0; j < 4; j++) {
                float4 w = *(const float4*)(W + c * 128 + kc + k0 + j * 4);
                Ws[k0 + j * 4 + 0][c] = w.x;
                Ws[k0 + j * 4 + 1][c] = w.y;
                Ws[k0 + j * 4 + 2][c] = w.z;
                Ws[k0 + j * 4 + 3][c] = w.w;
            }
        }
        {
            int r = t >> 2;
            int k0 = (t & 3) * 8;
            int row = rbase + r;
            float4 a0 = make_float4(0.f, 0.f, 0.f, 0.f), a1 = a0;
            if (row < NN) {
                a0 = *(const float4*)(h + (size_t)row * 128 + kc + k0);
                a1 = *(const float4*)(h + (size_t)row * 128 + kc + k0 + 4);
            }
            *(float4*)&Hs[r][k0] = a0;
            *(float4*)&Hs[r][k0 + 4] = a1;
        }
        __syncthreads();

#pragma unroll
        for (int k = 0; k < 32; k += 4) {
            float4 w0 = *(const float4*)&Ws[k + 0][tx * 4];
            float4 w1 = *(const float4*)&Ws[k + 1][tx * 4];
            float4 w2 = *(const float4*)&Ws[k + 2][tx * 4];
            float4 w3 = *(const float4*)&Ws[k + 3][tx * 4];
#pragma unroll
            for (int i = 0; i < 8; i++) {
                float4 hv = *(const float4*)&Hs[ty * 8 + i][k];
                acc[i][0] += hv.x * w0.x; acc[i][1] += hv.x * w0.y;
                acc[i][2] += hv.x * w0.z; acc[i][3] += hv.x * w0.w;
                acc[i][0] += hv.y * w1.x; acc[i][1] += hv.y * w1.y;
                acc[i][2] += hv.y * w1.z; acc[i][3] += hv.y * w1.w;
                acc[i][0] += hv.z * w2.x; acc[i][1] += hv.z * w2.y;
                acc[i][2] += hv.z * w2.z; acc[i][3] += hv.z * w2.w;
                acc[i][0] += hv.w * w3.x; acc[i][1] += hv.w * w3.y;
                acc[i][2] += hv.w * w3.z; acc[i][3] += hv.w * w3.w;
            }
        }
    }

    int head = tx >> 3;
    int dd = (tx & 7) * 4;
    float4 av1 = *(const float4*)(a + head * 64 + dd);
    float4 av2 = *(const float4*)(a + head * 64 + 32 + dd);

#pragma unroll
    for (int i = 0; i < 8; i++) {
        int row = rbase + ty * 8 + i;
        bool ok = row < NN;
        if (ok) {
            *(float4*)(g_Wh + (size_t)row * 128 + tx * 4) =
                make_float4(acc[i][0], acc[i][1], acc[i][2], acc[i][3]);
        }
        float p1 = acc[i][0] * av1.x + acc[i][1] * av1.y + acc[i][2] * av1.z + acc[i][3] * av1.w;
        float p2 = acc[i][0] * av2.x + acc[i][1] * av2.y + acc[i][2] * av2.z + acc[i][3] * av2.w;
#pragma unroll
        for (int o = 1; o < 8; o <<= 1) {
            p1 += __shfl_xor_sync(0xffffffffu, p1, o);
            p2 += __shfl_xor_sync(0xffffffffu, p2, o);
        }
        if (ok && (tx & 7) == 0) {
            g_s1[row * 4 + head] = p1;
            g_s2[row * 4 + head] = p2;
        }
    }
}

// -------- per-edge logit helper (lanes 0-3 compute one head each) --------
__device__ __forceinline__ float edge_p(int s, int eid, float s2d, int lane,
                                        const float* __restrict__ ef,
                                        const float* __restrict__ sWe) {
    float p = 0.f;
    if (lane < 4) {
        float tv = g_s1[s * 4 + lane] + s2d;
        tv = tv > 0.f ? tv : 0.2f * tv;
        float ws = 0.f;
#pragma unroll
        for (int j = 0; j < 4; j++) {
            float4 e4 = *(const float4*)(ef + (size_t)eid * 16 + j * 4);
            float4 w4 = *(const float4*)(sWe + lane * 16 + j * 4);
            ws += e4.x * w4.x + e4.y * w4.y + e4.z * w4.z + e4.w * w4.w;
        }
        p = expf(tv + ws);
    }
    return p;
}

// -------- fused gather/softmax/aggregate/gelu/LN: one warp per dst node --------
__global__ void k_nodeagg(const float* __restrict__ ef, const float* __restrict__ We,
                          const float* __restrict__ scale, const float* __restrict__ bias,
                          float* __restrict__ out) {
    __shared__ float sWe[64];
    if (threadIdx.x < 64) sWe[threadIdx.x] = We[threadIdx.x];
    __syncthreads();

    int n = (int)((blockIdx.x * (unsigned)blockDim.x + threadIdx.x) >> 5);
    if (n >= NN) return;
    int lane = threadIdx.x & 31;
    int hsel = lane >> 3;

    int off0 = g_off[n];
    int off1 = g_off[n + 1];
    float s2d = (lane < 4) ? g_s2[n * 4 + lane] : 0.f;

    float a0 = 0.f, a1 = 0.f, a2 = 0.f, a3 = 0.f;
    float den = 0.f;

    int o = off0;
    // 2-wide software pipeline for MLP
    for (; o + 1 < off1; o += 2) {
        int2 ea = g_csr[o];
        int2 eb = g_csr[o + 1];
        float4 wva = *(const float4*)(g_Wh + (size_t)ea.x * 128 + lane * 4);
        float4 wvb = *(const float4*)(g_Wh + (size_t)eb.x * 128 + lane * 4);
        float pa = edge_p(ea.x, ea.y, s2d, lane, ef, sWe);
        float pb = edge_p(eb.x, eb.y, s2d, lane, ef, sWe);
        den += pa + pb;
        float pha = __shfl_sync(0xffffffffu, pa, hsel);
        float phb = __shfl_sync(0xffffffffu, pb, hsel);
        a0 += wva.x * pha + wvb.x * phb;
        a1 += wva.y * pha + wvb.y * phb;
        a2 += wva.z * pha + wvb.z * phb;
        a3 += wva.w * pha + wvb.w * phb;
    }
    if (o < off1) {
        int2 ea = g_csr[o];
        float4 wva = *(const float4*)(g_Wh + (size_t)ea.x * 128 + lane * 4);
        float pa = edge_p(ea.x, ea.y, s2d, lane, ef, sWe);
        den += pa;
        float pha = __shfl_sync(0xffffffffu, pa, hsel);
        a0 += wva.x * pha;
        a1 += wva.y * pha;
        a2 += wva.z * pha;
        a3 += wva.w * pha;
    }

    float dh = __shfl_sync(0xffffffffu, den, hsel);
    float inv = 1.f / (dh + 1e-9f);
    float x[4] = {a0 * inv, a1 * inv, a2 * inv, a3 * inv};

#pragma unroll
    for (int j = 0; j < 4; j++) {
        float xx = x[j];
        x[j] = 0.5f * xx * (1.f + erff(xx * 0.70710678118654752f));
    }

    float sum = x[0] + x[1] + x[2] + x[3];
    float sq = x[0] * x[0] + x[1] * x[1] + x[2] * x[2] + x[3] * x[3];
#pragma unroll
    for (int off = 16; off > 0; off >>= 1) {
        sum += __shfl_xor_sync(0xffffffffu, sum, off);
        sq += __shfl_xor_sync(0xffffffffu, sq, off);
    }
    float mu = sum * (1.f / 128.f);
    float var = sq * (1.f / 128.f) - mu * mu;
    float rstd = rsqrtf(var + 1e-5f);

    float4 sc = *(const float4*)(scale + lane * 4);
    float4 bi = *(const float4*)(bias + lane * 4);
    float4 o4;
    o4.x = (x[0] - mu) * rstd * sc.x + bi.x;
    o4.y = (x[1] - mu) * rstd * sc.y + bi.y;
    o4.z = (x[2] - mu) * rstd * sc.z + bi.z;
    o4.w = (x[3] - mu) * rstd * sc.w + bi.w;
    *(float4*)(out + (size_t)n * 128 + lane * 4) = o4;
}

extern "C" void kernel_launch(void* const* d_in, const int* in_sizes, int n_in,
                              void* d_out, int out_size) {
    int ih = 0, iei = 1, ief = 2, iW = 3, iWe = 4, ia = 5, isc = 6, ibi = 7;
    {
        int fh = -1, fei = -1, fef = -1, fW = -1, fWe = -1, fa = -1, fsc = -1, fbi = -1;
        for (int i = 0; i < n_in; i++) {
            int s = in_sizes[i];
            if (s == NN * IND) fh = i;
            else if (s == 2 * NE) fei = i;
            else if (s == NE * 16) fef = i;
            else if (s == OUTD * IND) fW = i;
            else if (s == NH * 16) fWe = i;
            else if (s == NH * 2 * HD) fa = i;
            else if (s == OUTD) { if (fsc < 0) fsc = i; else fbi = i; }
        }
        if (fh >= 0 && fei >= 0 && fef >= 0 && fW >= 0 && fWe >= 0 && fa >= 0 &&
            fsc >= 0 && fbi >= 0) {
            ih = fh; iei = fei; ief = fef; iW = fW; iWe = fWe; ia = fa;
            isc = fsc; ibi = fbi;
        }
    }
    const float* h = (const float*)d_in[ih];
    const void* ei = d_in[iei];
    const float* ef = (const float*)d_in[ief];
    const float* W = (const float*)d_in[iW];
    const float* We = (const float*)d_in[iWe];
    const float* a = (const float*)d_in[ia];
    const float* sc = (const float*)d_in[isc];
    const float* bi = (const float*)d_in[ibi];
    float* out = (float*)d_out;

    k_detect<<<1, 32>>>(ei);
    k_decode<<<(2 * NE + 255) / 256, 256>>>(ei);
    k_zero<<<(NN + 255) / 256, 256>>>();
    k_count<<<(NE + 255) / 256, 256>>>();
    k_scan<<<1, 1024>>>();
    k_fill<<<(NE + 255) / 256, 256>>>();
    k_gemm<<<(NN + 63) / 64, 256>>>(h, W, a);
    k_nodeagg<<<(NN * 32 + 255) / 256, 256>>>(ef, We, sc, bi, out);
}

// round 7
// speedup vs baseline: 1.1869x; 1.1869x over previous
#include <cuda_runtime.h>
#include <cstdint>

#define NN 50000
#define NE 640000
#define IND 128
#define OUTD 128
#define NH 4
#define HD 32

// -------- scratch --------
__device__ __align__(16) float g_Wh[(size_t)NN * OUTD];    // 25.6 MB
__device__ __align__(16) float g_agg[(size_t)NN * OUTD];   // 25.6 MB
__device__ __align__(16) float g_s1[NN * NH];
__device__ __align__(16) float g_s2[NN * NH];
__device__ __align__(16) float g_den[NN * NH];
__device__ __align__(16) int   g_src[NE];
__device__ __align__(16) int   g_dst[NE];

// f32x2 packed-FMA helpers (SASS FFMA2; PTX-only path)
#define PACK2(r, lo, hi) asm("mov.b64 %0, {%1, %2};" : "=l"(r) : "f"(lo), "f"(hi))
#define UNPACK2(lo, hi, r) asm("mov.b64 {%0, %1}, %2;" : "=f"(lo), "=f"(hi) : "l"(r))
#define FMA_X2(c, a, b) asm("fma.rn.f32x2 %0, %1, %2, %0;" : "+l"(c) : "l"(a), "l"(b))

// -------- init: zero agg/den --------
__global__ void k_init() {
    int i = blockIdx.x * blockDim.x + threadIdx.x;
    int stride = gridDim.x * blockDim.x;
    float4 z = make_float4(0.f, 0.f, 0.f, 0.f);
    float4* agg4 = (float4*)g_agg;
    float4* den4 = (float4*)g_den;
    for (int t = i; t < NN * 32; t += stride) agg4[t] = z;
    for (int t = i; t < NN; t += stride) den4[t] = z;
}

// -------- GEMM: Wh = h @ W^T (f32x2 FFMA2 inner loop), fused s1/s2 dots --------
__global__ void k_gemm(const float* __restrict__ h, const float* __restrict__ W,
                       const float* __restrict__ a) {
    __shared__ float Ws[32][128];
    __shared__ float Hs[64][32];

    int t = threadIdx.x;
    int tx = t & 31;
    int ty = t >> 5;
    int rbase = blockIdx.x * 64;

    unsigned long long acc01[8], acc23[8];
#pragma unroll
    for (int i = 0; i < 8; i++) { acc01[i] = 0ull; acc23[i] = 0ull; }

    for (int kc = 0; kc < 128; kc += 32) {
        __syncthreads();
        {
            int c = t >> 1;
            int k0 = (t & 1) * 16;
#pragma unroll
            for (int j = 0; j < 4; j++) {
                float4 w = *(const float4*)(W + c * 128 + kc + k0 + j * 4);
                Ws[k0 + j * 4 + 0][c] = w.x;
                Ws[k0 + j * 4 + 1][c] = w.y;
                Ws[k0 + j * 4 + 2][c] = w.z;
                Ws[k0 + j * 4 + 3][c] = w.w;
            }
        }
        {
            int r = t >> 2;
            int k0 = (t & 3) * 8;
            int row = rbase + r;
            float4 a0 = make_float4(0.f, 0.f, 0.f, 0.f), a1 = a0;
            if (row < NN) {
                a0 = *(const float4*)(h + (size_t)row * 128 + kc + k0);
                a1 = *(const float4*)(h + (size_t)row * 128 + kc + k0 + 4);
            }
            *(float4*)&Hs[r][k0] = a0;
            *(float4*)&Hs[r][k0 + 4] = a1;
        }
        __syncthreads();

#pragma unroll
        for (int k = 0; k < 32; k += 4) {
            // load + pack 4 w-vectors for this lane's 4 columns
            unsigned long long w01[4], w23[4];
#pragma unroll
            for (int kk = 0; kk < 4; kk++) {
                float4 w = *(const float4*)&Ws[k + kk][tx * 4];
                PACK2(w01[kk], w.x, w.y);
                PACK2(w23[kk], w.z, w.w);
            }
#pragma unroll
            for (int i = 0; i < 8; i++) {
                float4 hv = *(const float4*)&Hs[ty * 8 + i][k];
                unsigned long long hh;
                PACK2(hh, hv.x, hv.x);
                FMA_X2(acc01[i], hh, w01[0]); FMA_X2(acc23[i], hh, w23[0]);
                PACK2(hh, hv.y, hv.y);
                FMA_X2(acc01[i], hh, w01[1]); FMA_X2(acc23[i], hh, w23[1]);
                PACK2(hh, hv.z, hv.z);
                FMA_X2(acc01[i], hh, w01[2]); FMA_X2(acc23[i], hh, w23[2]);
                PACK2(hh, hv.w, hv.w);
                FMA_X2(acc01[i], hh, w01[3]); FMA_X2(acc23[i], hh, w23[3]);
            }
        }
    }

    int head = tx >> 3;
    int dd = (tx & 7) * 4;
    float4 av1 = *(const float4*)(a + head * 64 + dd);
    float4 av2 = *(const float4*)(a + head * 64 + 32 + dd);

#pragma unroll
    for (int i = 0; i < 8; i++) {
        float c0, c1, c2, c3;
        UNPACK2(c0, c1, acc01[i]);
        UNPACK2(c2, c3, acc23[i]);
        int row = rbase + ty * 8 + i;
        bool ok = row < NN;
        if (ok) {
            *(float4*)(g_Wh + (size_t)row * 128 + tx * 4) = make_float4(c0, c1, c2, c3);
        }
        float p1 = c0 * av1.x + c1 * av1.y + c2 * av1.z + c3 * av1.w;
        float p2 = c0 * av2.x + c1 * av2.y + c2 * av2.z + c3 * av2.w;
#pragma unroll
        for (int o = 1; o < 8; o <<= 1) {
            p1 += __shfl_xor_sync(0xffffffffu, p1, o);
            p2 += __shfl_xor_sync(0xffffffffu, p2, o);
        }
        if (ok && (tx & 7) == 0) {
            g_s1[row * 4 + head] = p1;
            g_s2[row * 4 + head] = p2;
        }
    }
}

// -------- decode edge_index (per-block width detection) --------
__global__ void k_decode(const void* __restrict__ ei) {
    // sample high words within the always-safe first NE uint2 region
    int samp = (int)(((unsigned)blockIdx.x * 2654435761u + threadIdx.x) % (unsigned)NE);
    unsigned hiw = ((const uint2*)ei)[samp].y;
    int any = __syncthreads_or(hiw != 0u);
    int is64 = !any;

    int i = blockIdx.x * blockDim.x + threadIdx.x;
    if (i >= 2 * NE) return;
    long long v;
    if (is64) v = ((const long long*)ei)[i];
    else      v = (long long)((const int*)ei)[i];
    int iv = (int)v;
    iv = iv < 0 ? 0 : (iv >= NN ? NN - 1 : iv);
    if (i < NE) g_src[i] = iv;
    else        g_dst[i - NE] = iv;
}

// -------- fused edge pass: logits, exp, denom, v4-RED scatter (warp/edge) --------
__global__ void k_edge_full(const float* __restrict__ ef, const float* __restrict__ We) {
    __shared__ float sWe[64];
    if (threadIdx.x < 64) sWe[threadIdx.x] = We[threadIdx.x];
    __syncthreads();

    int e = (int)((blockIdx.x * (unsigned)blockDim.x + threadIdx.x) >> 5);
    int lane = threadIdx.x & 31;
    if (e >= NE) return;

    int s = g_src[e];
    int d = g_dst[e];

    float p = 0.f;
    if (lane < 4) {
        float s1 = g_s1[s * 4 + lane];
        float s2 = g_s2[d * 4 + lane];
        float tv = s1 + s2;
        tv = tv > 0.f ? tv : 0.2f * tv;
        float wsum = 0.f;
#pragma unroll
        for (int j = 0; j < 4; j++) {
            float4 efv = *(const float4*)(ef + (size_t)e * 16 + j * 4);
            float4 wv = *(const float4*)(sWe + lane * 16 + j * 4);
            wsum += efv.x * wv.x + efv.y * wv.y + efv.z * wv.z + efv.w * wv.w;
        }
        p = expf(tv + wsum);
        atomicAdd(&g_den[d * 4 + lane], p);
    }
    float ph = __shfl_sync(0xffffffffu, p, lane >> 3);

    float4 w = *(const float4*)(g_Wh + (size_t)s * 128 + lane * 4);
    unsigned long long dst =
        (unsigned long long)__cvta_generic_to_global(g_agg + (size_t)d * 128 + lane * 4);
    asm volatile("red.global.add.v4.f32 [%0], {%1,%2,%3,%4};"
                 :: "l"(dst), "f"(w.x * ph), "f"(w.y * ph), "f"(w.z * ph), "f"(w.w * ph)
                 : "memory");
}

// -------- node pass: normalize, gelu (exact), layernorm (one warp/node) --------
__global__ void k_node(const float* __restrict__ scale,
                       const float* __restrict__ bias,
                       float* __restrict__ out) {
    int n = (int)((blockIdx.x * (unsigned)blockDim.x + threadIdx.x) >> 5);
    if (n >= NN) return;
    int lane = threadIdx.x & 31;
    int head = lane >> 3;

    float den = g_den[n * 4 + head] + 1e-9f;
    float inv = 1.f / den;
    float4 v = *(const float4*)(g_agg + (size_t)n * 128 + lane * 4);
    float x[4] = {v.x * inv, v.y * inv, v.z * inv, v.w * inv};

#pragma unroll
    for (int j = 0; j < 4; j++) {
        float xx = x[j];
        x[j] = 0.5f * xx * (1.f + erff(xx * 0.70710678118654752f));
    }

    float sum = x[0] + x[1] + x[2] + x[3];
    float sq = x[0] * x[0] + x[1] * x[1] + x[2] * x[2] + x[3] * x[3];
#pragma unroll
    for (int o = 16; o > 0; o >>= 1) {
        sum += __shfl_xor_sync(0xffffffffu, sum, o);
        sq += __shfl_xor_sync(0xffffffffu, sq, o);
    }
    float mu = sum * (1.f / 128.f);
    float var = sq * (1.f / 128.f) - mu * mu;
    float rstd = rsqrtf(var + 1e-5f);

    float4 sc = *(const float4*)(scale + lane * 4);
    float4 bi = *(const float4*)(bias + lane * 4);
    float4 o4;
    o4.x = (x[0] - mu) * rstd * sc.x + bi.x;
    o4.y = (x[1] - mu) * rstd * sc.y + bi.y;
    o4.z = (x[2] - mu) * rstd * sc.z + bi.z;
    o4.w = (x[3] - mu) * rstd * sc.w + bi.w;
    *(float4*)(out + (size_t)n * 128 + lane * 4) = o4;
}

extern "C" void kernel_launch(void* const* d_in, const int* in_sizes, int n_in,
                              void* d_out, int out_size) {
    int ih = 0, iei = 1, ief = 2, iW = 3, iWe = 4, ia = 5, isc = 6, ibi = 7;
    {
        int fh = -1, fei = -1, fef = -1, fW = -1, fWe = -1, fa = -1, fsc = -1, fbi = -1;
        for (int i = 0; i < n_in; i++) {
            int s = in_sizes[i];
            if (s == NN * IND) fh = i;
            else if (s == 2 * NE) fei = i;
            else if (s == NE * 16) fef = i;
            else if (s == OUTD * IND) fW = i;
            else if (s == NH * 16) fWe = i;
            else if (s == NH * 2 * HD) fa = i;
            else if (s == OUTD) { if (fsc < 0) fsc = i; else fbi = i; }
        }
        if (fh >= 0 && fei >= 0 && fef >= 0 && fW >= 0 && fWe >= 0 && fa >= 0 &&
            fsc >= 0 && fbi >= 0) {
            ih = fh; iei = fei; ief = fef; iW = fW; iWe = fWe; ia = fa;
            isc = fsc; ibi = fbi;
        }
    }
    const float* h = (const float*)d_in[ih];
    const void* ei = d_in[iei];
    const float* ef = (const float*)d_in[ief];
    const float* W = (const float*)d_in[iW];
    const float* We = (const float*)d_in[iWe];
    const float* a = (const float*)d_in[ia];
    const float* sc = (const float*)d_in[isc];
    const float* bi = (const float*)d_in[ibi];
    float* out = (float*)d_out;

    // order chosen so the 4th launch (the one ncu profiles) is k_edge_full
    k_init<<<2048, 256>>>();
    k_gemm<<<(NN + 63) / 64, 256>>>(h, W, a);
    k_decode<<<(2 * NE + 255) / 256, 256>>>(ei);
    k_edge_full<<<(NE + 7) / 8, 256>>>(ef, We);
    k_node<<<(NN * 32 + 255) / 256, 256>>>(sc, bi, out);
}